// round 1
// baseline (speedup 1.0000x reference)
#include <cuda_runtime.h>
#include <math.h>

#define NB   16
#define TQ   2048
#define TV   2048
#define DEC  1024
#define ENC  512

// ---------------- scratch (device globals; no allocation allowed) ----------
__device__ float g_keys [(size_t)NB * TV * DEC];   // 128 MB
__device__ float g_probs[(size_t)NB * TQ * TV];    // 256 MB  (scores, then probs in place)

// ---------------- generic 128x128x8 fp32 GEMM ------------------------------
// C[m,n] = sum_k A[m,k] * B[k,n]   (TRANS_B: B element (k,n) read at B[n*ldb+k])
// EPI==1: add bias[n]
template<bool TRANS_B, int EPI>
__global__ __launch_bounds__(256, 2)
void gemm128(const float* __restrict__ A, const float* __restrict__ Bm,
             float* __restrict__ C, const float* __restrict__ bias,
             int lda, int ldb, int ldc,
             long long strideA, long long strideB, long long strideC,
             int K)
{
    __shared__ float As[8][128];
    __shared__ float Bs[8][128];

    const int bz = blockIdx.z;
    A  += (long long)bz * strideA;
    Bm += (long long)bz * strideB;
    C  += (long long)bz * strideC;

    const int tid     = threadIdx.x;            // 0..255
    const int rowBase = blockIdx.y * 128;
    const int colBase = blockIdx.x * 128;

    const int arow = tid >> 1;
    const int acol = (tid & 1) * 4;

    const int tm = (tid >> 4) * 8;
    const int tn = (tid & 15) * 8;

    float acc[8][8];
#pragma unroll
    for (int i = 0; i < 8; i++)
#pragma unroll
        for (int j = 0; j < 8; j++) acc[i][j] = 0.f;

    for (int k0 = 0; k0 < K; k0 += 8) {
        // stage A tile (128 rows x 8 k), transposed into As[k][m]
        float4 av = *(const float4*)(A + (long long)(rowBase + arow) * lda + k0 + acol);
        As[acol + 0][arow] = av.x;
        As[acol + 1][arow] = av.y;
        As[acol + 2][arow] = av.z;
        As[acol + 3][arow] = av.w;

        if (TRANS_B) {
            const int bn = tid >> 1;
            const int bk = (tid & 1) * 4;
            float4 bv = *(const float4*)(Bm + (long long)(colBase + bn) * ldb + k0 + bk);
            Bs[bk + 0][bn] = bv.x;
            Bs[bk + 1][bn] = bv.y;
            Bs[bk + 2][bn] = bv.z;
            Bs[bk + 3][bn] = bv.w;
        } else {
            const int bk = tid >> 5;
            const int bn = (tid & 31) * 4;
            float4 bv = *(const float4*)(Bm + (long long)(k0 + bk) * ldb + colBase + bn);
            *(float4*)&Bs[bk][bn] = bv;
        }
        __syncthreads();

#pragma unroll
        for (int kk = 0; kk < 8; kk++) {
            float a[8], b[8];
#pragma unroll
            for (int i = 0; i < 8; i++) a[i] = As[kk][tm + i];
#pragma unroll
            for (int j = 0; j < 8; j++) b[j] = Bs[kk][tn + j];
#pragma unroll
            for (int i = 0; i < 8; i++)
#pragma unroll
                for (int j = 0; j < 8; j++) acc[i][j] += a[i] * b[j];
        }
        __syncthreads();
    }

    float bv[8];
    if (EPI == 1) {
#pragma unroll
        for (int j = 0; j < 8; j++) bv[j] = bias[colBase + tn + j];
    }

#pragma unroll
    for (int i = 0; i < 8; i++) {
        const long long r = rowBase + tm + i;
#pragma unroll
        for (int j = 0; j < 8; j += 4) {
            float4 v;
            v.x = acc[i][j + 0];
            v.y = acc[i][j + 1];
            v.z = acc[i][j + 2];
            v.w = acc[i][j + 3];
            if (EPI == 1) {
                v.x += bv[j + 0]; v.y += bv[j + 1];
                v.z += bv[j + 2]; v.w += bv[j + 3];
            }
            *(float4*)(C + r * ldc + colBase + tn + j) = v;
        }
    }
}

// ---------------- row softmax over TV, in place -----------------------------
__global__ __launch_bounds__(256)
void softmax_rows(float* __restrict__ P)
{
    const long long row = blockIdx.x;
    float* p = P + row * (long long)TV;
    const int tid = threadIdx.x;

    float vals[8];
    float lmax = -3.0e38f;
#pragma unroll
    for (int i = 0; i < 2; i++) {
        float4 t = ((const float4*)p)[tid + i * 256];
        vals[i * 4 + 0] = t.x; vals[i * 4 + 1] = t.y;
        vals[i * 4 + 2] = t.z; vals[i * 4 + 3] = t.w;
        lmax = fmaxf(lmax, fmaxf(fmaxf(t.x, t.y), fmaxf(t.z, t.w)));
    }

    __shared__ float red[256];
    red[tid] = lmax;
    __syncthreads();
    for (int s = 128; s > 0; s >>= 1) {
        if (tid < s) red[tid] = fmaxf(red[tid], red[tid + s]);
        __syncthreads();
    }
    const float m = red[0];
    __syncthreads();

    float lsum = 0.f;
#pragma unroll
    for (int i = 0; i < 8; i++) {
        vals[i] = expf(vals[i] - m);
        lsum += vals[i];
    }
    red[tid] = lsum;
    __syncthreads();
    for (int s = 128; s > 0; s >>= 1) {
        if (tid < s) red[tid] += red[tid + s];
        __syncthreads();
    }
    const float inv = 1.f / red[0];

#pragma unroll
    for (int i = 0; i < 2; i++) {
        float4 t;
        t.x = vals[i * 4 + 0] * inv; t.y = vals[i * 4 + 1] * inv;
        t.z = vals[i * 4 + 2] * inv; t.w = vals[i * 4 + 3] * inv;
        ((float4*)p)[tid + i * 256] = t;
    }
}

// ---------------- transpose [b,q,v] -> [b,v,q] ------------------------------
__global__ __launch_bounds__(256)
void transpose_bqv(const float* __restrict__ in, float* __restrict__ out)
{
    __shared__ float t[32][33];
    const int b = blockIdx.z;
    const float* src = in  + (long long)b * TQ * TV;
    float*       dst = out + (long long)b * TV * TQ;

    const int v0 = blockIdx.x * 32;
    const int q0 = blockIdx.y * 32;

    for (int i = threadIdx.y; i < 32; i += 8)
        t[i][threadIdx.x] = src[(long long)(q0 + i) * TV + v0 + threadIdx.x];
    __syncthreads();
    for (int i = threadIdx.y; i < 32; i += 8)
        dst[(long long)(v0 + i) * TQ + q0 + threadIdx.x] = t[threadIdx.x][i];
}

// ---------------- copy query into context columns [512:1536) ---------------
__global__ __launch_bounds__(256)
void copy_query(const float* __restrict__ q, float* __restrict__ out)
{
    // each thread moves one float4 of query; out row stride 1536 floats (384 f4)
    const long long idx = (long long)blockIdx.x * 256 + threadIdx.x; // in float4 units
    const long long row = idx >> 8;          // query row stride 1024 floats = 256 f4
    const long long c4  = idx & 255;
    ((float4*)out)[row * 384 + 128 + c4] = ((const float4*)q)[idx];
}

// ---------------- launch -----------------------------------------------------
extern "C" void kernel_launch(void* const* d_in, const int* in_sizes, int n_in,
                              void* d_out, int out_size)
{
    (void)in_sizes; (void)n_in; (void)out_size;
    const float* q    = (const float*)d_in[0];   // [16,2048,1024]
    const float* v    = (const float*)d_in[1];   // [16,2048,512]
    const float* W    = (const float*)d_in[2];   // [512,1024]
    const float* bias = (const float*)d_in[3];   // [1024]

    float* out       = (float*)d_out;
    float* out_ctx   = out;                                      // [16,2048,1536]
    float* out_align = out + (long long)NB * TQ * 1536;          // [16,2048,2048]

    float* keys = nullptr;
    float* probs = nullptr;
    cudaGetSymbolAddress((void**)&keys,  g_keys);
    cudaGetSymbolAddress((void**)&probs, g_probs);

    // K1: keys = value @ W + bias    [per b: 2048x1024x512]
    gemm128<false, 1><<<dim3(DEC / 128, TV / 128, NB), 256>>>(
        v, W, keys, bias,
        ENC, DEC, DEC,
        (long long)TV * ENC, 0LL, (long long)TV * DEC,
        ENC);

    // K2: scores = query @ keys^T    [per b: 2048x2048x1024]
    gemm128<true, 0><<<dim3(TV / 128, TQ / 128, NB), 256>>>(
        q, keys, probs, nullptr,
        DEC, DEC, TV,
        (long long)TQ * DEC, (long long)TV * DEC, (long long)TQ * TV,
        DEC);

    // K3: softmax rows (in place)
    softmax_rows<<<NB * TQ, 256>>>(probs);

    // K4: context = probs @ value   [per b: 2048x512x2048], ldc=1536 into out
    gemm128<false, 0><<<dim3(ENC / 128, TQ / 128, NB), 256>>>(
        probs, v, out_ctx, nullptr,
        TV, ENC, 1536,
        (long long)TQ * TV, (long long)TV * ENC, (long long)TQ * 1536,
        TV);

    // K5: alignment_t = transpose(probs)
    transpose_bqv<<<dim3(TV / 32, TQ / 32, NB), dim3(32, 8)>>>(probs, out_align);

    // K6: concat query into context region
    copy_query<<<(NB * TQ * (DEC / 4)) / 256, 256>>>(q, out_ctx);
}

// round 4
// speedup vs baseline: 2.7975x; 2.7975x over previous
#include <cuda_runtime.h>
#include <cuda_bf16.h>
#include <math.h>
#include <stdint.h>

#define NB   16
#define TQ   2048
#define TV   2048
#define DEC  1024
#define ENC  512

// ---------------- scratch (device globals; no allocation allowed) ----------
__device__ __nv_bfloat16 g_q3   [(size_t)NB * TQ * (3 * DEC)];   // query  split P [hi,hi,lo]
__device__ __nv_bfloat16 g_v3   [(size_t)NB * TV * (3 * ENC)];   // value  split P
__device__ __nv_bfloat16 g_wt3  [(size_t)DEC * (3 * ENC)];       // W^T    split Q [hi,lo,hi]
__device__ __nv_bfloat16 g_vt3  [(size_t)NB * ENC * (3 * TV)];   // value^T split Q
__device__ __nv_bfloat16 g_keys3[(size_t)NB * TV * (3 * DEC)];   // keys   split Q (GEMM1 epilogue)
__device__ __nv_bfloat16 g_p3   [(size_t)NB * TQ * (3 * TV)];    // probs  split P (softmax)
__device__ float         g_scores[(size_t)NB * TQ * TV];         // fp32 scores

// ========================= PTX helpers =====================================
static __device__ __forceinline__ uint32_t smem_u32(const void* p) {
    uint32_t a;
    asm("{ .reg .u64 t; cvta.to.shared.u64 t, %1; cvt.u32.u64 %0, t; }"
        : "=r"(a) : "l"(p));
    return a;
}

#define CP_ASYNC16(dst, src) \
    asm volatile("cp.async.cg.shared.global [%0], [%1], 16;" :: "r"(dst), "l"(src) : "memory")
#define CP_COMMIT() asm volatile("cp.async.commit_group;" ::: "memory")
#define CP_WAIT1()  asm volatile("cp.async.wait_group 1;" ::: "memory")
#define CP_WAIT0()  asm volatile("cp.async.wait_group 0;" ::: "memory")

#define LDMX4(r0, r1, r2, r3, addr) \
    asm volatile("ldmatrix.sync.aligned.m8n8.x4.shared.b16 {%0,%1,%2,%3}, [%4];" \
        : "=r"(r0), "=r"(r1), "=r"(r2), "=r"(r3) : "r"(addr))

#define MMA_BF16(d, a, b) \
    asm volatile("mma.sync.aligned.m16n8k16.row.col.f32.bf16.bf16.f32 " \
        "{%0,%1,%2,%3}, {%4,%5,%6,%7}, {%8,%9}, {%0,%1,%2,%3};" \
        : "+f"((d)[0]), "+f"((d)[1]), "+f"((d)[2]), "+f"((d)[3]) \
        : "r"((a)[0]), "r"((a)[1]), "r"((a)[2]), "r"((a)[3]), \
          "r"((b)[0]), "r"((b)[1]))

#define SMEM_SWZ(off) ((off) ^ (((off) >> 3) & 0x70))

static __device__ __forceinline__ void split2(float v, __nv_bfloat16& h, __nv_bfloat16& l) {
    h = __float2bfloat16(v);
    l = __float2bfloat16(v - __bfloat162float(h));
}

// ========================= mma.sync GEMM ===================================
// C[128x128 tile] = A[M,K3] * B[N,K3]^T  (both K-major bf16)
// EPI=0: fp32 store (C, ldc, sC).  EPI=1: keys3 split-Q store + bias.
#define TILE_BYTES 16384u
#define STAGE_BYTES (2u * TILE_BYTES)
#define GEMM_DSMEM (2 * 32768 + 1024)

template<int EPI>
__global__ __launch_bounds__(256, 2)
void gemm_mma(const __nv_bfloat16* __restrict__ A, const __nv_bfloat16* __restrict__ B,
              float* __restrict__ C, const float* __restrict__ bias,
              __nv_bfloat16* __restrict__ O3,
              int K3, long long sA, long long sB, long long sC, int ldc)
{
    extern __shared__ char dsm[];
    const int tid  = threadIdx.x;
    const int wid  = tid >> 5;
    const int lane = tid & 31;
    const int bz   = blockIdx.z;
    const int rowBase = blockIdx.y * 128;
    const int colBase = blockIdx.x * 128;
    const int nIter = K3 >> 6;

    const int warp_m = wid & 3;          // 0..3  -> 32-row slab
    const int warp_n = wid >> 2;         // 0..1  -> 64-col slab

    const uint32_t tile0 = (smem_u32(dsm) + 1023u) & ~1023u;   // [A0][B0][A1][B1]

    const char* gA = (const char*)(A + bz * sA);
    const char* gB = (const char*)(B + bz * sB);
    const int cr = tid >> 3;             // 0..31
    const int ch = (tid & 7) * 16;       // 16B chunk in 128B row
    const long long ldab = (long long)K3 * 2;

    auto fill = [&](int buf, int i) {
        const uint32_t tA = tile0 + (uint32_t)buf * STAGE_BYTES;
        const uint32_t tB = tA + TILE_BYTES;
        const long long kb = (long long)i * 128;   // 64 bf16 = 128 bytes
#pragma unroll
        for (int r = 0; r < 4; r++) {
            const int rit = r * 32 + cr;
            const uint32_t so = SMEM_SWZ((uint32_t)(rit * 128 + ch));
            CP_ASYNC16(tA + so, gA + (long long)(rowBase + rit) * ldab + kb + ch);
            CP_ASYNC16(tB + so, gB + (long long)(colBase + rit) * ldab + kb + ch);
        }
        CP_COMMIT();
    };

    float acc[2][8][4];
#pragma unroll
    for (int mt = 0; mt < 2; mt++)
#pragma unroll
        for (int nt = 0; nt < 8; nt++)
#pragma unroll
            for (int c = 0; c < 4; c++) acc[mt][nt][c] = 0.f;

    // per-lane ldmatrix addressing
    const int lrow = lane & 7;
    const int lg   = lane >> 3;          // 0..3 address group

    fill(0, 0);
    for (int i = 0; i < nIter; i++) {
        const int buf = i & 1;
        if (i + 1 < nIter) { fill(buf ^ 1, i + 1); CP_WAIT1(); }
        else               { CP_WAIT0(); }
        __syncthreads();

        const uint32_t tA = tile0 + (uint32_t)buf * STAGE_BYTES;
        const uint32_t tB = tA + TILE_BYTES;

#pragma unroll
        for (int ks = 0; ks < 4; ks++) {
            const int kb = ks * 16;
            uint32_t af[2][4];
#pragma unroll
            for (int mt = 0; mt < 2; mt++) {
                // groups: g0: m0-7,k0 | g1: m8-15,k0 | g2: m0-7,k8 | g3: m8-15,k8
                const int row = warp_m * 32 + mt * 16 + (lg & 1) * 8 + lrow;
                const int kk  = kb + (lg >> 1) * 8;
                LDMX4(af[mt][0], af[mt][1], af[mt][2], af[mt][3],
                      tA + SMEM_SWZ((uint32_t)(row * 128 + kk * 2)));
            }
            uint32_t bf[8][2];
#pragma unroll
            for (int nt2 = 0; nt2 < 4; nt2++) {
                // groups: g0: n0-7,k0 | g1: n0-7,k8 | g2: n8-15,k0 | g3: n8-15,k8
                const int nn = warp_n * 64 + nt2 * 16 + (lg >> 1) * 8 + lrow;
                const int kk = kb + (lg & 1) * 8;
                uint32_t r0, r1, r2, r3;
                LDMX4(r0, r1, r2, r3, tB + SMEM_SWZ((uint32_t)(nn * 128 + kk * 2)));
                bf[2 * nt2][0] = r0;     bf[2 * nt2][1] = r1;
                bf[2 * nt2 + 1][0] = r2; bf[2 * nt2 + 1][1] = r3;
            }
#pragma unroll
            for (int mt = 0; mt < 2; mt++)
#pragma unroll
                for (int nt = 0; nt < 8; nt++)
                    MMA_BF16(acc[mt][nt], af[mt], bf[nt]);
        }
        __syncthreads();
    }

    // -------- epilogue (acc in registers) ----------------------------------
    const int erow = (lane >> 2);        // 0..7
    const int ecol = (lane & 3) * 2;

    if (EPI == 0) {
        float* cb = C + bz * sC;
#pragma unroll
        for (int mt = 0; mt < 2; mt++) {
#pragma unroll
            for (int nt = 0; nt < 8; nt++) {
                const long long r0 = rowBase + warp_m * 32 + mt * 16 + erow;
                const int cc = colBase + warp_n * 64 + nt * 8 + ecol;
                float2 lo = make_float2(acc[mt][nt][0], acc[mt][nt][1]);
                float2 hi = make_float2(acc[mt][nt][2], acc[mt][nt][3]);
                *(float2*)(cb + r0 * ldc + cc)       = lo;
                *(float2*)(cb + (r0 + 8) * ldc + cc) = hi;
            }
        }
    } else {
        // keys3: +bias, split bf16 [hi | lo | hi] at col offsets 0/1024/2048
        __nv_bfloat16* ob = O3 + bz * (3072LL * TV);
#pragma unroll
        for (int mt = 0; mt < 2; mt++) {
#pragma unroll
            for (int nt = 0; nt < 8; nt++) {
                const int cc = colBase + warp_n * 64 + nt * 8 + ecol;
                const float b0 = bias[cc], b1 = bias[cc + 1];
#pragma unroll
                for (int half = 0; half < 2; half++) {
                    const long long r0 = rowBase + warp_m * 32 + mt * 16 + erow + 8 * half;
                    const float f0 = acc[mt][nt][2 * half + 0] + b0;
                    const float f1 = acc[mt][nt][2 * half + 1] + b1;
                    __nv_bfloat16 h0, l0, h1, l1;
                    split2(f0, h0, l0);
                    split2(f1, h1, l1);
                    __nv_bfloat16* o = ob + r0 * 3072LL + cc;
                    __nv_bfloat162 hp = __halves2bfloat162(h0, h1);
                    *(__nv_bfloat162*)(o)        = hp;
                    *(__nv_bfloat162*)(o + 1024) = __halves2bfloat162(l0, l1);
                    *(__nv_bfloat162*)(o + 2048) = hp;
                }
            }
        }
    }
}

// ========================= conversion kernels ==============================
// fp32 [rows,K] -> bf16 [rows,3K]  layout P = [hi | hi | lo]
__global__ __launch_bounds__(256)
void conv_P(const float* __restrict__ in, __nv_bfloat16* __restrict__ out, int K)
{
    const long long idx = (long long)blockIdx.x * 256 + threadIdx.x;   // float4 id
    const int K4 = K >> 2;
    const long long row = idx / K4;
    const int c = (int)(idx - row * K4) * 4;
    float4 v = ((const float4*)in)[idx];
    __nv_bfloat16 h[4], l[4];
    split2(v.x, h[0], l[0]); split2(v.y, h[1], l[1]);
    split2(v.z, h[2], l[2]); split2(v.w, h[3], l[3]);
    __nv_bfloat16* ob = out + row * (3LL * K) + c;
    ((__nv_bfloat162*)ob)[0]           = __halves2bfloat162(h[0], h[1]);
    ((__nv_bfloat162*)ob)[1]           = __halves2bfloat162(h[2], h[3]);
    ((__nv_bfloat162*)(ob + K))[0]     = __halves2bfloat162(h[0], h[1]);
    ((__nv_bfloat162*)(ob + K))[1]     = __halves2bfloat162(h[2], h[3]);
    ((__nv_bfloat162*)(ob + 2 * K))[0] = __halves2bfloat162(l[0], l[1]);
    ((__nv_bfloat162*)(ob + 2 * K))[1] = __halves2bfloat162(l[2], l[3]);
}

// fp32 [b][R,C] -> bf16 [b][C,3R]  layout Q = [hi | lo | hi] (transpose+split)
__global__ void conv_QT(const float* __restrict__ in, __nv_bfloat16* __restrict__ out,
                        int R, int C)
{
    __shared__ float t[32][33];
    const long long bi = blockIdx.z;
    const float* src = in + bi * (long long)R * C;
    __nv_bfloat16* dst = out + bi * (long long)C * 3 * R;
    const int c0 = blockIdx.x * 32, r0 = blockIdx.y * 32;
    const int tx = threadIdx.x;
    for (int i = threadIdx.y; i < 32; i += 8)
        t[i][tx] = src[(long long)(r0 + i) * C + c0 + tx];
    __syncthreads();
    for (int i = threadIdx.y; i < 32; i += 8) {
        __nv_bfloat16 h, l;
        split2(t[tx][i], h, l);
        const long long ob = (long long)(c0 + i) * 3 * R + r0 + tx;
        dst[ob] = h; dst[ob + R] = l; dst[ob + 2 * R] = h;
    }
}

// softmax rows + split to p3 layout P = [hi | hi | lo] over 3*TV
__global__ __launch_bounds__(256)
void softmax_split(const float* __restrict__ S, __nv_bfloat16* __restrict__ P3)
{
    const long long row = blockIdx.x;
    const float* p = S + row * (long long)TV;
    __nv_bfloat16* o = P3 + row * (3LL * TV);
    const int tid = threadIdx.x;

    float vals[8];
    float lmax = -3.0e38f;
#pragma unroll
    for (int i = 0; i < 2; i++) {
        float4 t = ((const float4*)p)[tid + i * 256];
        vals[i * 4 + 0] = t.x; vals[i * 4 + 1] = t.y;
        vals[i * 4 + 2] = t.z; vals[i * 4 + 3] = t.w;
        lmax = fmaxf(lmax, fmaxf(fmaxf(t.x, t.y), fmaxf(t.z, t.w)));
    }

    __shared__ float red[256];
    red[tid] = lmax;
    __syncthreads();
    for (int s = 128; s > 0; s >>= 1) {
        if (tid < s) red[tid] = fmaxf(red[tid], red[tid + s]);
        __syncthreads();
    }
    const float m = red[0];
    __syncthreads();

    float lsum = 0.f;
#pragma unroll
    for (int i = 0; i < 8; i++) { vals[i] = expf(vals[i] - m); lsum += vals[i]; }
    red[tid] = lsum;
    __syncthreads();
    for (int s = 128; s > 0; s >>= 1) {
        if (tid < s) red[tid] += red[tid + s];
        __syncthreads();
    }
    const float inv = 1.f / red[0];

#pragma unroll
    for (int i = 0; i < 2; i++) {
        const int e0 = 4 * tid + 1024 * i;
        __nv_bfloat16 h[4], l[4];
#pragma unroll
        for (int t = 0; t < 4; t++) split2(vals[i * 4 + t] * inv, h[t], l[t]);
        __nv_bfloat16* ob = o + e0;
        ((__nv_bfloat162*)ob)[0]            = __halves2bfloat162(h[0], h[1]);
        ((__nv_bfloat162*)ob)[1]            = __halves2bfloat162(h[2], h[3]);
        ((__nv_bfloat162*)(ob + TV))[0]     = __halves2bfloat162(h[0], h[1]);
        ((__nv_bfloat162*)(ob + TV))[1]     = __halves2bfloat162(h[2], h[3]);
        ((__nv_bfloat162*)(ob + 2 * TV))[0] = __halves2bfloat162(l[0], l[1]);
        ((__nv_bfloat162*)(ob + 2 * TV))[1] = __halves2bfloat162(l[2], l[3]);
    }
}

// alignment_t: transpose (hi+lo) of p3 -> fp32 [b][v][q]
__global__ void transpose_out(const __nv_bfloat16* __restrict__ P3, float* __restrict__ out)
{
    __shared__ float t[32][33];
    const int b = blockIdx.z;
    const __nv_bfloat16* base = P3 + (long long)b * TQ * (3LL * TV);
    float* dst = out + (long long)b * TV * TQ;
    const int v0 = blockIdx.x * 32, q0 = blockIdx.y * 32;
    const int tx = threadIdx.x;
    for (int i = threadIdx.y; i < 32; i += 8) {
        const long long rb = (long long)(q0 + i) * (3LL * TV) + v0 + tx;
        t[i][tx] = __bfloat162float(base[rb]) + __bfloat162float(base[rb + 2 * TV]);
    }
    __syncthreads();
    for (int i = threadIdx.y; i < 32; i += 8)
        dst[(long long)(v0 + i) * TQ + q0 + tx] = t[tx][i];
}

// copy query into context columns [512:1536)
__global__ __launch_bounds__(256)
void copy_query(const float* __restrict__ q, float* __restrict__ out)
{
    const long long idx = (long long)blockIdx.x * 256 + threadIdx.x;  // float4 id
    const long long row = idx >> 8;
    const long long c4  = idx & 255;
    ((float4*)out)[row * 384 + 128 + c4] = ((const float4*)q)[idx];
}

// ========================= launch ==========================================
extern "C" void kernel_launch(void* const* d_in, const int* in_sizes, int n_in,
                              void* d_out, int out_size)
{
    (void)in_sizes; (void)n_in; (void)out_size;
    const float* q    = (const float*)d_in[0];   // [16,2048,1024]
    const float* v    = (const float*)d_in[1];   // [16,2048,512]
    const float* W    = (const float*)d_in[2];   // [512,1024]
    const float* bias = (const float*)d_in[3];   // [1024]

    float* out       = (float*)d_out;
    float* out_ctx   = out;                                      // [16,2048,1536]
    float* out_align = out + (long long)NB * TQ * 1536;          // [16,2048,2048]

    __nv_bfloat16 *q3, *v3, *wt3, *vt3, *keys3, *p3;
    float* scores;
    cudaGetSymbolAddress((void**)&q3,     g_q3);
    cudaGetSymbolAddress((void**)&v3,     g_v3);
    cudaGetSymbolAddress((void**)&wt3,    g_wt3);
    cudaGetSymbolAddress((void**)&vt3,    g_vt3);
    cudaGetSymbolAddress((void**)&keys3,  g_keys3);
    cudaGetSymbolAddress((void**)&p3,     g_p3);
    cudaGetSymbolAddress((void**)&scores, g_scores);

    cudaFuncSetAttribute(gemm_mma<0>, cudaFuncAttributeMaxDynamicSharedMemorySize, GEMM_DSMEM);
    cudaFuncSetAttribute(gemm_mma<1>, cudaFuncAttributeMaxDynamicSharedMemorySize, GEMM_DSMEM);

    // operand prep
    conv_P<<<(NB * TQ * (DEC / 4)) / 256, 256>>>(q, q3, DEC);                 // query -> P
    conv_P<<<(NB * TV * (ENC / 4)) / 256, 256>>>(v, v3, ENC);                 // value -> P
    conv_QT<<<dim3(DEC / 32, ENC / 32, 1),  dim3(32, 8)>>>(W, wt3, ENC, DEC); // W^T   -> Q
    conv_QT<<<dim3(ENC / 32, TV / 32, NB),  dim3(32, 8)>>>(v, vt3, TV, ENC);  // val^T -> Q

    // K1: keys3 = split(value @ W + b)   [M=TV, N=DEC, K3=1536]
    gemm_mma<1><<<dim3(DEC / 128, TV / 128, NB), 256, GEMM_DSMEM>>>(
        v3, wt3, nullptr, bias, keys3,
        3 * ENC, (long long)TV * (3 * ENC), 0LL, 0LL, 0);

    // K2: scores = query @ keys^T        [M=TQ, N=TV, K3=3072]
    gemm_mma<0><<<dim3(TV / 128, TQ / 128, NB), 256, GEMM_DSMEM>>>(
        q3, keys3, scores, nullptr, nullptr,
        3 * DEC, (long long)TQ * (3 * DEC), (long long)TV * (3 * DEC),
        (long long)TQ * TV, TV);

    // K3: softmax + split probs
    softmax_split<<<NB * TQ, 256>>>(scores, p3);

    // K4: context = probs @ value        [M=TQ, N=ENC, K3=6144]
    gemm_mma<0><<<dim3(ENC / 128, TQ / 128, NB), 256, GEMM_DSMEM>>>(
        p3, vt3, out_ctx, nullptr, nullptr,
        3 * TV, (long long)TQ * (3 * TV), (long long)ENC * (3 * TV),
        (long long)TQ * 1536, 1536);

    // K5: alignment_t
    transpose_out<<<dim3(TV / 32, TQ / 32, NB), dim3(32, 8)>>>(p3, out_align);

    // K6: concat query
    copy_query<<<(NB * TQ * (DEC / 4)) / 256, 256>>>(q, out_ctx);
}